// round 17
// baseline (speedup 1.0000x reference)
#include <cuda_runtime.h>
#include <cstdint>

// Problem constants
#define B_DIM 128
#define G_DIM 20000
#define N_ELEM (B_DIM * G_DIM)   // 2,560,000
#define HID 64
#define NBM1 9                   // NUM_BINS - 1
#define NBINS 10
#define NSEG (HID + 1)           // 65 piecewise-linear segments
#define ROWF 20                  // floats per table row (A0..A8,C0..C8,pad,pad) = 80B
#define BLK 256
#define NTILE (N_ELEM / BLK)     // 10,000 tiles of 256 elements
#define PGRID 1184               // persistent CTAs: 148 SMs x 8
#define LOG2E 1.4426950408889634f

// ---------------------------------------------------------------------------
// Single fused kernel.
//
// Prologue (per CTA, once): build the piecewise-linear table in smem.
//   logit_k(x) = b2[k] + sum_h W2[h,k] * leaky(x*w1[h] + b1[h]) is piecewise
//   linear in x with breakpoints thr_h = -b1[h]/w1[h]. For segment j (x
//   between sorted thresholds T[j-1], T[j]):
//     w1>0 : pre-act >= 0  <=>  rank(thr_h) < j
//     w1<0 : pre-act >= 0  <=>  rank(thr_h) >= j
//     w1==0: pre-act >= 0  <=>  b1 >= 0    (thr=+inf, excluded from search)
//   Entry (j,k): logit = A*x + C, stored pre-scaled by log2(e) for exp2f.
//
// Main loop (persistent, ~8.5 tiles of 256 elements per CTA):
//   compaction of nonzeros -> ~26 threads run search+softmax; output rows
//   assembled in a double-buffered 10KB staging area; flushed with one
//   cp.async.bulk per tile (async proxy; no LSU/L1 on the flush path),
//   wait_group.read 1 pipelines the drain behind the next tile's compute.
// ---------------------------------------------------------------------------
__global__ void __launch_bounds__(BLK)
expr_quantizer_kernel(const float* __restrict__ expr,
                      const float* __restrict__ W1,
                      const float* __restrict__ b1,
                      const float* __restrict__ W2,
                      const float* __restrict__ b2,
                      float* __restrict__ probs,
                      float* __restrict__ mask) {
    __shared__ __align__(16) float sOut[2][BLK * NBINS];  // 2 x 10 KB staging
    __shared__ __align__(16) float sTab[NSEG * ROWF];     // 5.2 KB table
    __shared__ float sT[HID];          // sorted thresholds
    __shared__ int   sRank[HID];
    __shared__ float sW1[HID];
    __shared__ float sB1[HID];
    __shared__ float s_xv[BLK];
    __shared__ int   s_xi[BLK];
    __shared__ int   s_cnt[2];

    int t = threadIdx.x;

    // ---- prologue: table build ----
    if (t < HID) {
        float w = __ldg(W1 + t);
        float b = __ldg(b1 + t);
        sW1[t] = w;
        sB1[t] = b;
        sT[t] = 0.0f;  // will be overwritten via rank scatter
        sRank[t] = 0;
    }
    if (t < 2) s_cnt[t] = 0;
    __syncthreads();

    if (t < HID) {
        float w = sW1[t];
        float thr = (w != 0.0f) ? (-sB1[t] / w) : __int_as_float(0x7f800000);
        // stable rank among all thresholds
        int idx = 0;
        #pragma unroll
        for (int h = 0; h < HID; h++) {
            float wo = sW1[h];
            float o = (wo != 0.0f) ? (-sB1[h] / wo) : __int_as_float(0x7f800000);
            if (o < thr || (o == thr && h < t)) idx++;
        }
        sRank[t] = idx;
        sT[idx] = thr;
    }
    __syncthreads();

    // 585 (segment, bin) entries, <=3 per thread
    for (int ent = t; ent < NSEG * NBM1; ent += BLK) {
        int j = ent / NBM1;
        int k = ent % NBM1;
        float A = 0.0f, C = 0.0f;
        #pragma unroll 8
        for (int h = 0; h < HID; h++) {
            float w = sW1[h];
            float b = sB1[h];
            bool pos;
            if (w > 0.0f)      pos = (sRank[h] < j);
            else if (w < 0.0f) pos = (sRank[h] >= j);
            else               pos = (b >= 0.0f);
            float scale = pos ? 1.0f : 0.01f;
            float w2s = __ldg(W2 + h * NBM1 + k) * scale;  // L1-hot after 1st entry
            A = fmaf(w2s, w, A);
            C = fmaf(w2s, b, C);
        }
        sTab[j * ROWF + k]        = A * LOG2E;
        sTab[j * ROWF + NBM1 + k] = (C + __ldg(b2 + k)) * LOG2E;
    }
    // zero row padding (r4 tail reads)
    for (int j = t; j < NSEG; j += BLK) {
        sTab[j * ROWF + 18] = 0.0f;
        sTab[j * ROWF + 19] = 0.0f;
    }
    __syncthreads();

    // ---- persistent main loop ----
    int it = 0;
    for (int tile = blockIdx.x; tile < NTILE; tile += PGRID, it++) {
        int b = it & 1;
        float* out = sOut[b];

        // phase A: load, mask, own-row init (5 x STS.64), compact nonzeros
        int e = tile * BLK + t;
        float x = __ldg(expr + e);
        bool nz = (x != 0.0f);
        {
            float2* row2 = reinterpret_cast<float2*>(out + t * NBINS);
            row2[0] = make_float2(nz ? 0.0f : 1.0f, 0.0f);
            float2 z2 = make_float2(0.0f, 0.0f);
            row2[1] = z2; row2[2] = z2; row2[3] = z2; row2[4] = z2;
        }
        mask[e] = nz ? 1.0f : 0.0f;
        if (t == 0) s_cnt[b ^ 1] = 0;       // reset other buffer's counter
        if (nz) {
            int p = atomicAdd(&s_cnt[b], 1);
            s_xv[p] = x;
            s_xi[p] = t;
        }
        __syncthreads();

        // phase B: first n threads run search + softmax
        int n = s_cnt[b];
        if (t < n) {
            float xx = s_xv[t];
            int idx = s_xi[t];

            // segment = count of sorted thresholds <= xx, in [0, 64]
            int sj = 0;
            #pragma unroll
            for (int step = 64; step > 0; step >>= 1) {
                int nj = sj + step;
                if (nj <= HID && sT[nj - 1] <= xx) sj = nj;
            }

            const float4* row = reinterpret_cast<const float4*>(sTab + sj * ROWF);
            float4 r0 = row[0];  // A0..A3
            float4 r1 = row[1];  // A4..A7
            float4 r2 = row[2];  // A8, C0, C1, C2
            float4 r3 = row[3];  // C3..C6
            float4 r4 = row[4];  // C7, C8, pad, pad

            float l0 = fmaf(r0.x, xx, r2.y);
            float l1 = fmaf(r0.y, xx, r2.z);
            float l2 = fmaf(r0.z, xx, r2.w);
            float l3 = fmaf(r0.w, xx, r3.x);
            float l4 = fmaf(r1.x, xx, r3.y);
            float l5 = fmaf(r1.y, xx, r3.z);
            float l6 = fmaf(r1.z, xx, r3.w);
            float l7 = fmaf(r1.w, xx, r4.x);
            float l8 = fmaf(r2.x, xx, r4.y);

            float m0 = fmaxf(l0, l1), m1 = fmaxf(l2, l3);
            float m2 = fmaxf(l4, l5), m3 = fmaxf(l6, l7);
            float mx = fmaxf(fmaxf(fmaxf(m0, m1), fmaxf(m2, m3)), l8);

            float e0 = exp2f(l0 - mx), e1 = exp2f(l1 - mx), e2 = exp2f(l2 - mx);
            float e3 = exp2f(l3 - mx), e4 = exp2f(l4 - mx), e5 = exp2f(l5 - mx);
            float e6 = exp2f(l6 - mx), e7 = exp2f(l7 - mx), e8 = exp2f(l8 - mx);

            float s0 = e0 + e1, s1 = e2 + e3, s2 = e4 + e5, s3 = e6 + e7;
            float sum = ((s0 + s1) + (s2 + s3)) + e8;
            float inv = __fdividef(1.0f, sum);

            float* o = out + idx * NBINS;
            o[1] = e0 * inv; o[2] = e1 * inv; o[3] = e2 * inv;
            o[4] = e3 * inv; o[5] = e4 * inv; o[6] = e5 * inv;
            o[7] = e6 * inv; o[8] = e7 * inv; o[9] = e8 * inv;
        }
        __syncthreads();

        // flush (pipelined): TMA reads smem via async proxy, writes L2
        if (t == 0) {
            asm volatile("fence.proxy.async.shared::cta;" ::: "memory");
            uint32_t ssrc = (uint32_t)__cvta_generic_to_shared(out);
            void* gdst = (void*)(probs + (size_t)tile * (BLK * NBINS));
            asm volatile(
                "cp.async.bulk.global.shared::cta.bulk_group [%0], [%1], %2;"
                :: "l"(gdst), "r"(ssrc), "n"(BLK * NBINS * 4) : "memory");
            asm volatile("cp.async.bulk.commit_group;" ::: "memory");
            // allow 1 in-flight group: the buffer we write next is drained
            asm volatile("cp.async.bulk.wait_group.read 1;" ::: "memory");
        }
        __syncthreads();   // gate: nobody refills the draining buffer early
    }

    // keep smem alive until the last TMA read completes
    if (t == 0) {
        asm volatile("cp.async.bulk.wait_group.read 0;" ::: "memory");
    }
}

extern "C" void kernel_launch(void* const* d_in, const int* in_sizes, int n_in,
                              void* d_out, int out_size) {
    const float* expr = (const float*)d_in[0];
    const float* W1   = (const float*)d_in[1];
    const float* b1   = (const float*)d_in[2];
    const float* W2   = (const float*)d_in[3];
    const float* b2   = (const float*)d_in[4];

    float* probs = (float*)d_out;
    float* maskp = (float*)d_out + (size_t)N_ELEM * NBINS;

    expr_quantizer_kernel<<<PGRID, BLK>>>(expr, W1, b1, W2, b2, probs, maskp);
}